// round 1
// baseline (speedup 1.0000x reference)
#include <cuda_runtime.h>
#include <math.h>

// Problem constants
#define B_  4
#define S_  1024
#define D_  1024
#define H_  16
#define NT  4096   // B*S tokens
#define BH  64     // B*H

// Scratch (static __device__ arrays — sanctioned, no cudaMalloc)
static __device__ float g_Q[(size_t)BH * S_ * 128];          // 32 MB  [b,h,s,128] (qa|qg)
static __device__ float g_K[(size_t)BH * S_ * 128];          // 32 MB  [b,h,s,128] (ka|kg)
static __device__ float g_V[(size_t)BH * S_ * 64];           // 16 MB  [b,h,s,64]
static __device__ float g_P[(size_t)BH * S_ * S_];           // 256 MB scores -> probs (in place)
static __device__ float g_X[(size_t)NT * D_];                // 16 MB  attn out [b,s,h*64+j]
static __device__ float g_G[(size_t)NT * D_];                // 16 MB  gate

// ---------------------------------------------------------------------------
// Core 128x128 tile SGEMM body: C[128,128] = A[m0:,:K] * B[n0:,:K]^T
// Both A and B are row-major with the K dimension contiguous.
// Optional concat A: columns >= ksplit come from A2 (lda2 = 1024).
// 256 threads, 8x8 micro-tile per thread (split 4+4 rows/cols to avoid
// shared-memory bank conflicts on the float4 LDS).
// ---------------------------------------------------------------------------
__device__ __forceinline__ void gemm128_body(
    const float* __restrict__ A, int lda,
    const float* __restrict__ A2, int ksplit,
    const float* __restrict__ Bm, int ldb,
    int K, int m0, int n0,
    float acc[8][8],
    float (*As)[128], float (*Bs)[128])
{
    const int tid  = threadIdx.x;
    const int arow = tid >> 1;           // 0..127
    const int acol = (tid & 1) << 2;     // 0 or 4
    const int ty   = tid >> 4;           // 0..15
    const int tx   = tid & 15;           // 0..15

    for (int k0 = 0; k0 < K; k0 += 8) {
        const int colA = k0 + acol;
        const float* ap = (colA >= ksplit)
            ? (A2 + (size_t)(m0 + arow) * 1024 + (colA - ksplit))
            : (A  + (size_t)(m0 + arow) * lda  + colA);
        float4 av = *(const float4*)ap;
        float4 bv = *(const float4*)(Bm + (size_t)(n0 + arow) * ldb + k0 + acol);

        __syncthreads();   // previous iteration's smem reads complete
        As[acol + 0][arow] = av.x;
        As[acol + 1][arow] = av.y;
        As[acol + 2][arow] = av.z;
        As[acol + 3][arow] = av.w;
        Bs[acol + 0][arow] = bv.x;
        Bs[acol + 1][arow] = bv.y;
        Bs[acol + 2][arow] = bv.z;
        Bs[acol + 3][arow] = bv.w;
        __syncthreads();

        #pragma unroll
        for (int kk = 0; kk < 8; kk++) {
            float a[8], b[8];
            #pragma unroll
            for (int i = 0; i < 4; i++) {
                a[i]     = As[kk][ty * 4 + i];
                a[4 + i] = As[kk][64 + ty * 4 + i];
                b[i]     = Bs[kk][tx * 4 + i];
                b[4 + i] = Bs[kk][64 + tx * 4 + i];
            }
            #pragma unroll
            for (int i = 0; i < 8; i++)
                #pragma unroll
                for (int j = 0; j < 8; j++)
                    acc[i][j] += a[i] * b[j];
        }
    }
}

__device__ __forceinline__ int tile_row(int base, int ty, int i) {
    return base + ((i < 4) ? (ty * 4 + i) : (64 + ty * 4 + (i - 4)));
}
__device__ __forceinline__ int tile_col(int base, int tx, int j) {
    return base + ((j < 4) ? (tx * 4 + j) : (64 + tx * 4 + (j - 4)));
}

// ---------------------------------------------------------------------------
// Kernel 1: the 5 head projections (qa,qg,ka,kg,va), grid.z selects which.
// Scatters results into [b,h,s,(0|64)+j] layout for Q/K concat and V.
// ---------------------------------------------------------------------------
__global__ __launch_bounds__(256) void proj_kernel(
    const float* __restrict__ qa_in, const float* __restrict__ qg_in,
    const float* __restrict__ ka_in, const float* __restrict__ kg_in,
    const float* __restrict__ va_in,
    const float* __restrict__ Wqa, const float* __restrict__ Wqg,
    const float* __restrict__ Wka, const float* __restrict__ Wkg,
    const float* __restrict__ Wva,
    const float* __restrict__ bqa, const float* __restrict__ bqg,
    const float* __restrict__ bka, const float* __restrict__ bkg,
    const float* __restrict__ bva)
{
    __shared__ float As[8][128];
    __shared__ float Bs[8][128];
    const int p = blockIdx.z;
    const float* A; const float* W; const float* bias;
    if      (p == 0) { A = qa_in; W = Wqa; bias = bqa; }
    else if (p == 1) { A = qg_in; W = Wqg; bias = bqg; }
    else if (p == 2) { A = ka_in; W = Wka; bias = bka; }
    else if (p == 3) { A = kg_in; W = Wkg; bias = bkg; }
    else             { A = va_in; W = Wva; bias = bva; }

    const int m0 = blockIdx.y * 128;
    const int n0 = blockIdx.x * 128;
    float acc[8][8] = {};
    gemm128_body(A, 1024, nullptr, 1 << 30, W, 1024, 1024, m0, n0, acc, As, Bs);

    const int ty = threadIdx.x >> 4, tx = threadIdx.x & 15;
    #pragma unroll
    for (int i = 0; i < 8; i++) {
        const int m = tile_row(m0, ty, i);
        const int b = m >> 10, s = m & 1023;
        #pragma unroll
        for (int j = 0; j < 8; j++) {
            const int n = tile_col(n0, tx, j);
            const int h = n >> 6, jj = n & 63;
            const float v = acc[i][j] + bias[n];
            const size_t row = (size_t)(b * 16 + h) * 1024 + s;
            if      (p == 0) g_Q[row * 128 + jj]      = v;
            else if (p == 1) g_Q[row * 128 + 64 + jj] = v;
            else if (p == 2) g_K[row * 128 + jj]      = v;
            else if (p == 3) g_K[row * 128 + 64 + jj] = v;
            else             g_V[row * 64 + jj]       = v;
        }
    }
}

// ---------------------------------------------------------------------------
// Kernel 2: gate = sigmoid(concat(query_a, query_g) @ Wgate^T + bgate)
// K = 2048 with split loader at 1024.
// ---------------------------------------------------------------------------
__global__ __launch_bounds__(256) void gate_kernel(
    const float* __restrict__ qa_in, const float* __restrict__ qg_in,
    const float* __restrict__ Wgate, const float* __restrict__ bgate)
{
    __shared__ float As[8][128];
    __shared__ float Bs[8][128];
    const int m0 = blockIdx.y * 128;
    const int n0 = blockIdx.x * 128;
    float acc[8][8] = {};
    gemm128_body(qa_in, 1024, qg_in, 1024, Wgate, 2048, 2048, m0, n0, acc, As, Bs);

    const int ty = threadIdx.x >> 4, tx = threadIdx.x & 15;
    #pragma unroll
    for (int i = 0; i < 8; i++) {
        const int m = tile_row(m0, ty, i);
        #pragma unroll
        for (int j = 0; j < 8; j++) {
            const int n = tile_col(n0, tx, j);
            const float z = acc[i][j] + bgate[n];
            g_G[(size_t)m * 1024 + n] = 1.0f / (1.0f + expf(-z));
        }
    }
}

// ---------------------------------------------------------------------------
// Kernel 3: scores = (Q @ K^T) / sqrt(128), masked. Batched over (b,h).
// ---------------------------------------------------------------------------
__global__ __launch_bounds__(256) void scores_kernel(const int* __restrict__ mask)
{
    __shared__ float As[8][128];
    __shared__ float Bs[8][128];
    const int bh = blockIdx.z;
    const int b  = bh >> 4;
    const float* Qp = g_Q + ((size_t)bh << 17);  // bh * 1024 * 128
    const float* Kp = g_K + ((size_t)bh << 17);
    const int m0 = blockIdx.y * 128;
    const int n0 = blockIdx.x * 128;
    float acc[8][8] = {};
    gemm128_body(Qp, 128, nullptr, 1 << 30, Kp, 128, 128, m0, n0, acc, As, Bs);

    const float scale = 0.0883883476483184405f;  // 1/sqrt(128)
    const int ty = threadIdx.x >> 4, tx = threadIdx.x & 15;
    #pragma unroll
    for (int i = 0; i < 8; i++) {
        const int m = tile_row(m0, ty, i);
        #pragma unroll
        for (int j = 0; j < 8; j++) {
            const int n = tile_col(n0, tx, j);
            float v = acc[i][j] * scale;
            if (mask[((size_t)b << 20) + (size_t)m * 1024 + n] == 0) v = -1e9f;
            g_P[((size_t)bh << 20) + (size_t)m * 1024 + n] = v;
        }
    }
}

// ---------------------------------------------------------------------------
// Kernel 4: row softmax over the 1024 keys, in place. 65536 rows.
// ---------------------------------------------------------------------------
__global__ __launch_bounds__(256) void softmax_kernel()
{
    const size_t row = blockIdx.x;
    float* p = g_P + (row << 10);
    const int tid = threadIdx.x;
    float4 v = *(float4*)(p + tid * 4);

    __shared__ float red[256];
    float m = fmaxf(fmaxf(v.x, v.y), fmaxf(v.z, v.w));
    red[tid] = m; __syncthreads();
    #pragma unroll
    for (int s = 128; s > 0; s >>= 1) {
        if (tid < s) red[tid] = fmaxf(red[tid], red[tid + s]);
        __syncthreads();
    }
    m = red[0]; __syncthreads();

    v.x = expf(v.x - m); v.y = expf(v.y - m);
    v.z = expf(v.z - m); v.w = expf(v.w - m);
    float sum = v.x + v.y + v.z + v.w;
    red[tid] = sum; __syncthreads();
    #pragma unroll
    for (int s = 128; s > 0; s >>= 1) {
        if (tid < s) red[tid] += red[tid + s];
        __syncthreads();
    }
    const float inv = 1.0f / red[0];
    v.x *= inv; v.y *= inv; v.z *= inv; v.w *= inv;
    *(float4*)(p + tid * 4) = v;
}

// ---------------------------------------------------------------------------
// Kernel 5: X = P @ V  (128x64 tile, K=1024), batched over (b,h).
// Writes g_X in [b, s, h*64+j] layout (= final [B,S,D]).
// ---------------------------------------------------------------------------
__global__ __launch_bounds__(256) void pv_kernel()
{
    __shared__ float As[8][128];
    __shared__ float Bs[8][64];
    const int bh = blockIdx.z;
    const float* P = g_P + ((size_t)bh << 20);
    const float* V = g_V + ((size_t)bh << 16);  // bh * 1024 * 64
    const int m0 = blockIdx.y * 128;
    const int tid = threadIdx.x;
    const int arow = tid >> 1, acol = (tid & 1) << 2;
    const int brow = tid >> 5, bcol = (tid & 31) << 1;
    const int ty = tid >> 4, tx = tid & 15;

    float acc[8][4] = {};
    for (int k0 = 0; k0 < 1024; k0 += 8) {
        float4 av = *(const float4*)(P + (size_t)(m0 + arow) * 1024 + k0 + acol);
        float2 bv = *(const float2*)(V + (size_t)(k0 + brow) * 64 + bcol);
        __syncthreads();
        As[acol + 0][arow] = av.x;
        As[acol + 1][arow] = av.y;
        As[acol + 2][arow] = av.z;
        As[acol + 3][arow] = av.w;
        Bs[brow][bcol]     = bv.x;
        Bs[brow][bcol + 1] = bv.y;
        __syncthreads();
        #pragma unroll
        for (int kk = 0; kk < 8; kk++) {
            float a[8], b4[4];
            #pragma unroll
            for (int i = 0; i < 4; i++) {
                a[i]     = As[kk][ty * 4 + i];
                a[4 + i] = As[kk][64 + ty * 4 + i];
            }
            #pragma unroll
            for (int j = 0; j < 4; j++) b4[j] = Bs[kk][tx * 4 + j];
            #pragma unroll
            for (int i = 0; i < 8; i++)
                #pragma unroll
                for (int j = 0; j < 4; j++)
                    acc[i][j] += a[i] * b4[j];
        }
    }

    const int b = bh >> 4, h = bh & 15;
    #pragma unroll
    for (int i = 0; i < 8; i++) {
        const int m = tile_row(m0, ty, i);
        #pragma unroll
        for (int j = 0; j < 4; j++) {
            const int c = tx * 4 + j;
            g_X[((size_t)(b * 1024 + m)) * 1024 + h * 64 + c] = acc[i][j];
        }
    }
}

// ---------------------------------------------------------------------------
// Kernel 6: out = gate * (X @ Winfo^T + binfo)
// ---------------------------------------------------------------------------
__global__ __launch_bounds__(256) void info_kernel(
    const float* __restrict__ Winfo, const float* __restrict__ binfo,
    float* __restrict__ out)
{
    __shared__ float As[8][128];
    __shared__ float Bs[8][128];
    const int m0 = blockIdx.y * 128;
    const int n0 = blockIdx.x * 128;
    float acc[8][8] = {};
    gemm128_body(g_X, 1024, nullptr, 1 << 30, Winfo, 1024, 1024, m0, n0, acc, As, Bs);

    const int ty = threadIdx.x >> 4, tx = threadIdx.x & 15;
    #pragma unroll
    for (int i = 0; i < 8; i++) {
        const int m = tile_row(m0, ty, i);
        #pragma unroll
        for (int j = 0; j < 8; j++) {
            const int n = tile_col(n0, tx, j);
            const float v = acc[i][j] + binfo[n];
            out[(size_t)m * 1024 + n] = g_G[(size_t)m * 1024 + n] * v;
        }
    }
}

// ---------------------------------------------------------------------------
extern "C" void kernel_launch(void* const* d_in, const int* in_sizes, int n_in,
                              void* d_out, int out_size)
{
    (void)in_sizes; (void)n_in; (void)out_size;
    const float* query_g = (const float*)d_in[0];
    const float* key_g   = (const float*)d_in[1];
    const float* query_a = (const float*)d_in[2];
    const float* key_a   = (const float*)d_in[3];
    const float* value_a = (const float*)d_in[4];
    const int*   mask    = (const int*)  d_in[5];
    const float* Wqg = (const float*)d_in[6];  const float* bqg = (const float*)d_in[7];
    const float* Wkg = (const float*)d_in[8];  const float* bkg = (const float*)d_in[9];
    const float* Wqa = (const float*)d_in[10]; const float* bqa = (const float*)d_in[11];
    const float* Wka = (const float*)d_in[12]; const float* bka = (const float*)d_in[13];
    const float* Wva = (const float*)d_in[14]; const float* bva = (const float*)d_in[15];
    const float* Wgate = (const float*)d_in[16]; const float* bgate = (const float*)d_in[17];
    const float* Winfo = (const float*)d_in[18]; const float* binfo = (const float*)d_in[19];

    dim3 blk(256);
    proj_kernel<<<dim3(8, 32, 5), blk>>>(query_a, query_g, key_a, key_g, value_a,
                                         Wqa, Wqg, Wka, Wkg, Wva,
                                         bqa, bqg, bka, bkg, bva);
    gate_kernel<<<dim3(8, 32, 1), blk>>>(query_a, query_g, Wgate, bgate);
    scores_kernel<<<dim3(8, 8, 64), blk>>>(mask);
    softmax_kernel<<<65536, blk>>>();
    pv_kernel<<<dim3(1, 8, 64), blk>>>();
    info_kernel<<<dim3(8, 32, 1), blk>>>(Winfo, binfo, (float*)d_out);
}

// round 2
// speedup vs baseline: 1.2388x; 1.2388x over previous
#include <cuda_runtime.h>
#include <math.h>
#include <stdint.h>

// Problem constants
#define B_  4
#define S_  1024
#define D_  1024
#define H_  16
#define NT  4096   // B*S tokens
#define BH  64     // B*H

// Scratch (static __device__ arrays — no cudaMalloc)
static __device__ float g_Q[(size_t)BH * S_ * 128];          // 32 MB  [b,h,s,128] (qa|qg)
static __device__ float g_K[(size_t)BH * S_ * 128];          // 32 MB  [b,h,s,128] (ka|kg)
static __device__ float g_V[(size_t)BH * S_ * 64];           // 16 MB  [b,h,s,64]
static __device__ float g_P[(size_t)BH * S_ * S_];           // 256 MB scores -> probs (in place)
static __device__ float g_X[(size_t)NT * D_];                // 16 MB  attn out
static __device__ float g_G[(size_t)NT * D_];                // 16 MB  gate

// ---------------------------------------------------------------------------
// TF32 helpers (3xTF32 split: hi = rna(x), lo = rna(x - hi))
// ---------------------------------------------------------------------------
__device__ __forceinline__ uint32_t f2tf(float x) {
    uint32_t r;
    asm("cvt.rna.tf32.f32 %0, %1;" : "=r"(r) : "f"(x));
    return r;
}

__device__ __forceinline__ void mma8(float* c,
    uint32_t a0, uint32_t a1, uint32_t a2, uint32_t a3,
    uint32_t b0, uint32_t b1)
{
    asm volatile(
        "mma.sync.aligned.m16n8k8.row.col.f32.tf32.tf32.f32 "
        "{%0,%1,%2,%3},{%4,%5,%6,%7},{%8,%9},{%0,%1,%2,%3};"
        : "+f"(c[0]), "+f"(c[1]), "+f"(c[2]), "+f"(c[3])
        : "r"(a0), "r"(a1), "r"(a2), "r"(a3), "r"(b0), "r"(b1));
}

// ---------------------------------------------------------------------------
// 128x128 C-tile TF32 GEMM body: C = A[m0:, :K] * B[n0:, :K]^T
// A,B row-major, K contiguous. Optional concat A (cols >= ksplit from A2,
// lda2 = 1024). 256 threads = 8 warps (4m x 2n), warp tile 32x64,
// mma.m16n8k8 with 3xTF32 split accumulation.
// smem: As[128][36], Bs[128][36]  (pad 4 -> conflict-free frag loads)
// ---------------------------------------------------------------------------
__device__ __forceinline__ void gemm_tf32_body(
    const float* __restrict__ A, int lda,
    const float* __restrict__ A2, int ksplit,
    const float* __restrict__ Bm, int ldb,
    int K, int m0, int n0,
    float acc[2][8][4],
    float (*As)[36], float (*Bs)[36])
{
    const int tid  = threadIdx.x;
    const int warp = tid >> 5, lane = tid & 31;
    const int wm = (warp & 3) * 32;
    const int wn = (warp >> 2) * 64;
    const int lr = lane >> 2;
    const int lc = lane & 3;
    const int k4 = (tid & 7) * 4;
    const int ar = tid >> 3;      // 0..31

    for (int k0 = 0; k0 < K; k0 += 32) {
        const int colA = k0 + k4;
        const float* abase;
        int ldaa;
        if (colA >= ksplit) { abase = A2 + (colA - ksplit); ldaa = 1024; }
        else                { abase = A  + colA;            ldaa = lda;  }

        __syncthreads();
        #pragma unroll
        for (int i = 0; i < 4; i++) {
            const int m = ar + i * 32;
            float4 v = *(const float4*)(abase + (size_t)(m0 + m) * ldaa);
            *(float4*)&As[m][k4] = v;
            float4 w = *(const float4*)(Bm + (size_t)(n0 + m) * ldb + k0 + k4);
            *(float4*)&Bs[m][k4] = w;
        }
        __syncthreads();

        #pragma unroll
        for (int kk = 0; kk < 32; kk += 8) {
            uint32_t ah[2][4], al[2][4];
            #pragma unroll
            for (int mt = 0; mt < 2; mt++) {
                #pragma unroll
                for (int q = 0; q < 4; q++) {
                    const int row = wm + mt * 16 + lr + (q & 1) * 8;
                    const int col = kk + lc + (q >> 1) * 4;
                    const float v = As[row][col];
                    const uint32_t h = f2tf(v);
                    ah[mt][q] = h;
                    al[mt][q] = f2tf(v - __uint_as_float(h));
                }
            }
            #pragma unroll
            for (int nf = 0; nf < 8; nf++) {
                uint32_t bhi[2], blo[2];
                #pragma unroll
                for (int q = 0; q < 2; q++) {
                    const float v = Bs[wn + nf * 8 + lr][kk + lc + q * 4];
                    const uint32_t h = f2tf(v);
                    bhi[q] = h;
                    blo[q] = f2tf(v - __uint_as_float(h));
                }
                #pragma unroll
                for (int mt = 0; mt < 2; mt++) {
                    mma8(acc[mt][nf], ah[mt][0], ah[mt][1], ah[mt][2], ah[mt][3], bhi[0], bhi[1]);
                    mma8(acc[mt][nf], ah[mt][0], ah[mt][1], ah[mt][2], ah[mt][3], blo[0], blo[1]);
                    mma8(acc[mt][nf], al[mt][0], al[mt][1], al[mt][2], al[mt][3], bhi[0], bhi[1]);
                }
            }
        }
    }
}

// Output element coordinates for the mma fragment layout:
// row = m0 + wm + mt*16 + lr + h2*8 ; cols = n0 + wn + nf*8 + 2*lc (+1)

// ---------------------------------------------------------------------------
// Kernel 1: 5 head projections, grid.z selects which.
// ---------------------------------------------------------------------------
__global__ __launch_bounds__(256) void proj_kernel(
    const float* __restrict__ qa_in, const float* __restrict__ qg_in,
    const float* __restrict__ ka_in, const float* __restrict__ kg_in,
    const float* __restrict__ va_in,
    const float* __restrict__ Wqa, const float* __restrict__ Wqg,
    const float* __restrict__ Wka, const float* __restrict__ Wkg,
    const float* __restrict__ Wva,
    const float* __restrict__ bqa, const float* __restrict__ bqg,
    const float* __restrict__ bka, const float* __restrict__ bkg,
    const float* __restrict__ bva)
{
    __shared__ float As[128][36];
    __shared__ float Bs[128][36];
    const int p = blockIdx.z;
    const float* A; const float* W; const float* bias;
    if      (p == 0) { A = qa_in; W = Wqa; bias = bqa; }
    else if (p == 1) { A = qg_in; W = Wqg; bias = bqg; }
    else if (p == 2) { A = ka_in; W = Wka; bias = bka; }
    else if (p == 3) { A = kg_in; W = Wkg; bias = bkg; }
    else             { A = va_in; W = Wva; bias = bva; }

    const int m0 = blockIdx.y * 128;
    const int n0 = blockIdx.x * 128;
    float acc[2][8][4] = {};
    gemm_tf32_body(A, 1024, nullptr, 1 << 30, W, 1024, 1024, m0, n0, acc, As, Bs);

    const int lane = threadIdx.x & 31, warp = threadIdx.x >> 5;
    const int wm = (warp & 3) * 32, wn = (warp >> 2) * 64;
    const int lr = lane >> 2, lc = lane & 3;

    #pragma unroll
    for (int nf = 0; nf < 8; nf++) {
        const int n  = n0 + wn + nf * 8 + 2 * lc;
        const int h  = n >> 6, jj = n & 63;
        const float bx = bias[n], by = bias[n + 1];
        #pragma unroll
        for (int mt = 0; mt < 2; mt++) {
            #pragma unroll
            for (int h2 = 0; h2 < 2; h2++) {
                const int m = m0 + wm + mt * 16 + lr + h2 * 8;
                const int b = m >> 10, s = m & 1023;
                const size_t row = (size_t)(b * 16 + h) * 1024 + s;
                float2 v;
                v.x = acc[mt][nf][h2 * 2 + 0] + bx;
                v.y = acc[mt][nf][h2 * 2 + 1] + by;
                if      (p == 0) *(float2*)&g_Q[row * 128 + jj]      = v;
                else if (p == 1) *(float2*)&g_Q[row * 128 + 64 + jj] = v;
                else if (p == 2) *(float2*)&g_K[row * 128 + jj]      = v;
                else if (p == 3) *(float2*)&g_K[row * 128 + 64 + jj] = v;
                else             *(float2*)&g_V[row * 64 + jj]       = v;
            }
        }
    }
}

// ---------------------------------------------------------------------------
// Kernel 2: gate = sigmoid(concat(query_a, query_g) @ Wgate^T + bgate), K=2048
// ---------------------------------------------------------------------------
__global__ __launch_bounds__(256) void gate_kernel(
    const float* __restrict__ qa_in, const float* __restrict__ qg_in,
    const float* __restrict__ Wgate, const float* __restrict__ bgate)
{
    __shared__ float As[128][36];
    __shared__ float Bs[128][36];
    const int m0 = blockIdx.y * 128;
    const int n0 = blockIdx.x * 128;
    float acc[2][8][4] = {};
    gemm_tf32_body(qa_in, 1024, qg_in, 1024, Wgate, 2048, 2048, m0, n0, acc, As, Bs);

    const int lane = threadIdx.x & 31, warp = threadIdx.x >> 5;
    const int wm = (warp & 3) * 32, wn = (warp >> 2) * 64;
    const int lr = lane >> 2, lc = lane & 3;

    #pragma unroll
    for (int nf = 0; nf < 8; nf++) {
        const int n = n0 + wn + nf * 8 + 2 * lc;
        const float bx = bgate[n], by = bgate[n + 1];
        #pragma unroll
        for (int mt = 0; mt < 2; mt++) {
            #pragma unroll
            for (int h2 = 0; h2 < 2; h2++) {
                const int m = m0 + wm + mt * 16 + lr + h2 * 8;
                float2 v;
                v.x = 1.0f / (1.0f + expf(-(acc[mt][nf][h2 * 2 + 0] + bx)));
                v.y = 1.0f / (1.0f + expf(-(acc[mt][nf][h2 * 2 + 1] + by)));
                *(float2*)&g_G[(size_t)m * 1024 + n] = v;
            }
        }
    }
}

// ---------------------------------------------------------------------------
// Kernel 3: scores = (Q @ K^T) / sqrt(128), masked. Batched over (b,h).
// ---------------------------------------------------------------------------
__global__ __launch_bounds__(256) void scores_kernel(const int* __restrict__ mask)
{
    __shared__ float As[128][36];
    __shared__ float Bs[128][36];
    const int bh = blockIdx.z;
    const int b  = bh >> 4;
    const float* Qp = g_Q + ((size_t)bh << 17);
    const float* Kp = g_K + ((size_t)bh << 17);
    const int m0 = blockIdx.y * 128;
    const int n0 = blockIdx.x * 128;
    float acc[2][8][4] = {};
    gemm_tf32_body(Qp, 128, nullptr, 1 << 30, Kp, 128, 128, m0, n0, acc, As, Bs);

    const float scale = 0.0883883476483184405f;  // 1/sqrt(128)
    const int lane = threadIdx.x & 31, warp = threadIdx.x >> 5;
    const int wm = (warp & 3) * 32, wn = (warp >> 2) * 64;
    const int lr = lane >> 2, lc = lane & 3;

    #pragma unroll
    for (int nf = 0; nf < 8; nf++) {
        const int n = n0 + wn + nf * 8 + 2 * lc;
        #pragma unroll
        for (int mt = 0; mt < 2; mt++) {
            #pragma unroll
            for (int h2 = 0; h2 < 2; h2++) {
                const int m = m0 + wm + mt * 16 + lr + h2 * 8;
                const int2 mk = *(const int2*)&mask[((size_t)b << 20) + (size_t)m * 1024 + n];
                float2 v;
                v.x = acc[mt][nf][h2 * 2 + 0] * scale;
                v.y = acc[mt][nf][h2 * 2 + 1] * scale;
                if (mk.x == 0) v.x = -1e9f;
                if (mk.y == 0) v.y = -1e9f;
                *(float2*)&g_P[((size_t)bh << 20) + (size_t)m * 1024 + n] = v;
            }
        }
    }
}

// ---------------------------------------------------------------------------
// Kernel 4: row softmax over 1024 keys, in place. 65536 rows.
// ---------------------------------------------------------------------------
__global__ __launch_bounds__(256) void softmax_kernel()
{
    const size_t row = blockIdx.x;
    float* p = g_P + (row << 10);
    const int tid = threadIdx.x;
    float4 v = *(float4*)(p + tid * 4);

    __shared__ float red[256];
    float m = fmaxf(fmaxf(v.x, v.y), fmaxf(v.z, v.w));
    red[tid] = m; __syncthreads();
    #pragma unroll
    for (int s = 128; s > 0; s >>= 1) {
        if (tid < s) red[tid] = fmaxf(red[tid], red[tid + s]);
        __syncthreads();
    }
    m = red[0]; __syncthreads();

    v.x = expf(v.x - m); v.y = expf(v.y - m);
    v.z = expf(v.z - m); v.w = expf(v.w - m);
    float sum = v.x + v.y + v.z + v.w;
    red[tid] = sum; __syncthreads();
    #pragma unroll
    for (int s = 128; s > 0; s >>= 1) {
        if (tid < s) red[tid] += red[tid + s];
        __syncthreads();
    }
    const float inv = 1.0f / red[0];
    v.x *= inv; v.y *= inv; v.z *= inv; v.w *= inv;
    *(float4*)(p + tid * 4) = v;
}

// ---------------------------------------------------------------------------
// Kernel 5: X = P @ V  (C tile 128x64, K=1024), batched over (b,h).
// B = V stored [k][n] (n contiguous) -> loaded directly as k-major smem tile.
// ---------------------------------------------------------------------------
__global__ __launch_bounds__(256) void pv_kernel()
{
    __shared__ float As[128][36];
    __shared__ float Bs[32][72];
    const int bh = blockIdx.z;
    const float* P = g_P + ((size_t)bh << 20);
    const float* V = g_V + ((size_t)bh << 16);
    const int m0 = blockIdx.y * 128;

    const int tid  = threadIdx.x;
    const int warp = tid >> 5, lane = tid & 31;
    const int wm = (warp & 3) * 32;
    const int wn = (warp >> 2) * 32;
    const int lr = lane >> 2, lc = lane & 3;
    const int k4 = (tid & 7) * 4;
    const int ar = tid >> 3;
    const int kb = tid >> 4;            // 0..15
    const int n4 = (tid & 15) * 4;

    float acc[2][4][4] = {};

    for (int k0 = 0; k0 < 1024; k0 += 32) {
        __syncthreads();
        #pragma unroll
        for (int i = 0; i < 4; i++) {
            const int m = ar + i * 32;
            float4 v = *(const float4*)(P + (size_t)(m0 + m) * 1024 + k0 + k4);
            *(float4*)&As[m][k4] = v;
        }
        #pragma unroll
        for (int i = 0; i < 2; i++) {
            const int k = kb + i * 16;
            float4 w = *(const float4*)(V + (size_t)(k0 + k) * 64 + n4);
            *(float4*)&Bs[k][n4] = w;
        }
        __syncthreads();

        #pragma unroll
        for (int kk = 0; kk < 32; kk += 8) {
            uint32_t ah[2][4], al[2][4];
            #pragma unroll
            for (int mt = 0; mt < 2; mt++) {
                #pragma unroll
                for (int q = 0; q < 4; q++) {
                    const int row = wm + mt * 16 + lr + (q & 1) * 8;
                    const int col = kk + lc + (q >> 1) * 4;
                    const float v = As[row][col];
                    const uint32_t h = f2tf(v);
                    ah[mt][q] = h;
                    al[mt][q] = f2tf(v - __uint_as_float(h));
                }
            }
            #pragma unroll
            for (int nf = 0; nf < 4; nf++) {
                uint32_t bhi[2], blo[2];
                #pragma unroll
                for (int q = 0; q < 2; q++) {
                    const float v = Bs[kk + lc + q * 4][wn + nf * 8 + lr];
                    const uint32_t h = f2tf(v);
                    bhi[q] = h;
                    blo[q] = f2tf(v - __uint_as_float(h));
                }
                #pragma unroll
                for (int mt = 0; mt < 2; mt++) {
                    mma8(acc[mt][nf], ah[mt][0], ah[mt][1], ah[mt][2], ah[mt][3], bhi[0], bhi[1]);
                    mma8(acc[mt][nf], ah[mt][0], ah[mt][1], ah[mt][2], ah[mt][3], blo[0], blo[1]);
                    mma8(acc[mt][nf], al[mt][0], al[mt][1], al[mt][2], al[mt][3], bhi[0], bhi[1]);
                }
            }
        }
    }

    const int b = bh >> 4, h = bh & 15;
    #pragma unroll
    for (int nf = 0; nf < 4; nf++) {
        const int c = wn + nf * 8 + 2 * lc;
        #pragma unroll
        for (int mt = 0; mt < 2; mt++) {
            #pragma unroll
            for (int h2 = 0; h2 < 2; h2++) {
                const int m = m0 + wm + mt * 16 + lr + h2 * 8;
                float2 v;
                v.x = acc[mt][nf][h2 * 2 + 0];
                v.y = acc[mt][nf][h2 * 2 + 1];
                *(float2*)&g_X[((size_t)(b * 1024 + m)) * 1024 + h * 64 + c] = v;
            }
        }
    }
}

// ---------------------------------------------------------------------------
// Kernel 6: out = gate * (X @ Winfo^T + binfo)
// ---------------------------------------------------------------------------
__global__ __launch_bounds__(256) void info_kernel(
    const float* __restrict__ Winfo, const float* __restrict__ binfo,
    float* __restrict__ out)
{
    __shared__ float As[128][36];
    __shared__ float Bs[128][36];
    const int m0 = blockIdx.y * 128;
    const int n0 = blockIdx.x * 128;
    float acc[2][8][4] = {};
    gemm_tf32_body(g_X, 1024, nullptr, 1 << 30, Winfo, 1024, 1024, m0, n0, acc, As, Bs);

    const int lane = threadIdx.x & 31, warp = threadIdx.x >> 5;
    const int wm = (warp & 3) * 32, wn = (warp >> 2) * 64;
    const int lr = lane >> 2, lc = lane & 3;

    #pragma unroll
    for (int nf = 0; nf < 8; nf++) {
        const int n = n0 + wn + nf * 8 + 2 * lc;
        const float bx = binfo[n], by = binfo[n + 1];
        #pragma unroll
        for (int mt = 0; mt < 2; mt++) {
            #pragma unroll
            for (int h2 = 0; h2 < 2; h2++) {
                const int m = m0 + wm + mt * 16 + lr + h2 * 8;
                const float2 g = *(const float2*)&g_G[(size_t)m * 1024 + n];
                float2 v;
                v.x = g.x * (acc[mt][nf][h2 * 2 + 0] + bx);
                v.y = g.y * (acc[mt][nf][h2 * 2 + 1] + by);
                *(float2*)&out[(size_t)m * 1024 + n] = v;
            }
        }
    }
}

// ---------------------------------------------------------------------------
extern "C" void kernel_launch(void* const* d_in, const int* in_sizes, int n_in,
                              void* d_out, int out_size)
{
    (void)in_sizes; (void)n_in; (void)out_size;
    const float* query_g = (const float*)d_in[0];
    const float* key_g   = (const float*)d_in[1];
    const float* query_a = (const float*)d_in[2];
    const float* key_a   = (const float*)d_in[3];
    const float* value_a = (const float*)d_in[4];
    const int*   mask    = (const int*)  d_in[5];
    const float* Wqg = (const float*)d_in[6];  const float* bqg = (const float*)d_in[7];
    const float* Wkg = (const float*)d_in[8];  const float* bkg = (const float*)d_in[9];
    const float* Wqa = (const float*)d_in[10]; const float* bqa = (const float*)d_in[11];
    const float* Wka = (const float*)d_in[12]; const float* bka = (const float*)d_in[13];
    const float* Wva = (const float*)d_in[14]; const float* bva = (const float*)d_in[15];
    const float* Wgate = (const float*)d_in[16]; const float* bgate = (const float*)d_in[17];
    const float* Winfo = (const float*)d_in[18]; const float* binfo = (const float*)d_in[19];

    dim3 blk(256);
    proj_kernel<<<dim3(8, 32, 5), blk>>>(query_a, query_g, key_a, key_g, value_a,
                                         Wqa, Wqg, Wka, Wkg, Wva,
                                         bqa, bqg, bka, bkg, bva);
    gate_kernel<<<dim3(8, 32, 1), blk>>>(query_a, query_g, Wgate, bgate);
    scores_kernel<<<dim3(8, 8, 64), blk>>>(mask);
    softmax_kernel<<<65536, blk>>>();
    pv_kernel<<<dim3(1, 8, 64), blk>>>();
    info_kernel<<<dim3(8, 32, 1), blk>>>(Winfo, binfo, (float*)d_out);
}

// round 3
// speedup vs baseline: 1.9203x; 1.5501x over previous
#include <cuda_runtime.h>
#include <cuda_bf16.h>
#include <math.h>
#include <stdint.h>

// Problem constants
#define B_  4
#define S_  1024
#define D_  1024
#define H_  16
#define BH  64     // B*H

// Scratch
static __device__ float g_Q[(size_t)BH * S_ * 128];   // [bh, s, 128] (qa|qg)
static __device__ float g_K[(size_t)BH * S_ * 128];   // [bh, s, 128] (ka|kg)
static __device__ float g_V[(size_t)BH * 64 * S_];    // TRANSPOSED [bh, j(64), s(1024)]
static __device__ float g_X[(size_t)B_ * S_ * D_];    // attn out [token][1024]
static __device__ float g_G[(size_t)B_ * S_ * D_];    // gate

// ---------------------------------------------------------------------------
// bf16 split helpers: x = hi + lo (+ tiny residual). Packed pairs (lo half =
// first/even element, matching mma fragment packing).
// ---------------------------------------------------------------------------
__device__ __forceinline__ void cvt_split2(float x, float y, uint32_t &hi, uint32_t &lo) {
    __nv_bfloat16 hx = __float2bfloat16_rn(x);
    __nv_bfloat16 hy = __float2bfloat16_rn(y);
    float rx = x - __bfloat162float(hx);
    float ry = y - __bfloat162float(hy);
    __nv_bfloat16 lx = __float2bfloat16_rn(rx);
    __nv_bfloat16 ly = __float2bfloat16_rn(ry);
    hi = (uint32_t)__bfloat16_as_ushort(hx) | ((uint32_t)__bfloat16_as_ushort(hy) << 16);
    lo = (uint32_t)__bfloat16_as_ushort(lx) | ((uint32_t)__bfloat16_as_ushort(ly) << 16);
}

__device__ __forceinline__ void mma_bf16(float* c,
    uint32_t a0, uint32_t a1, uint32_t a2, uint32_t a3,
    uint32_t b0, uint32_t b1)
{
    asm volatile(
        "mma.sync.aligned.m16n8k16.row.col.f32.bf16.bf16.f32 "
        "{%0,%1,%2,%3},{%4,%5,%6,%7},{%8,%9},{%0,%1,%2,%3};"
        : "+f"(c[0]), "+f"(c[1]), "+f"(c[2]), "+f"(c[3])
        : "r"(a0), "r"(a1), "r"(a2), "r"(a3), "r"(b0), "r"(b1));
}

// ---------------------------------------------------------------------------
// 128x128 C-tile GEMM body, C = A[m0:, :K] * B[n0:, :K]^T, bf16 3-way split.
// Conversion done once at smem-store time; smem holds packed bf16 pairs.
// 256 thr = 8 warps (4m x 2n), warp tile 32x64, mma m16n8k16.
// smem arrays: [128][20] uint32 (16 used cols + pad4, stride%32==4 -> no cfl).
// ---------------------------------------------------------------------------
typedef uint32_t (*SmT)[20];

__device__ __forceinline__ void gemm_bf16_body(
    const float* __restrict__ A, int lda,
    const float* __restrict__ A2, int ksplit,
    const float* __restrict__ Bm, int ldb,
    int K, int m0, int n0,
    float acc[2][8][4],
    SmT Ah, SmT Al, SmT Bh, SmT Bl)
{
    const int tid  = threadIdx.x;
    const int warp = tid >> 5, lane = tid & 31;
    const int wm = (warp & 3) * 32;
    const int wn = (warp >> 2) * 64;
    const int g  = lane >> 2;
    const int t  = lane & 3;
    const int k4 = (tid & 7) * 4;   // float col within 32-wide k tile
    const int ar = tid >> 3;        // 0..31

    for (int k0 = 0; k0 < K; k0 += 32) {
        const int colA = k0 + k4;
        const float* abase; int ldaa;
        if (colA >= ksplit) { abase = A2 + (colA - ksplit); ldaa = 1024; }
        else                { abase = A  + colA;            ldaa = lda;  }

        __syncthreads();
        #pragma unroll
        for (int i = 0; i < 4; i++) {
            const int m = ar + i * 32;
            const int pc = k4 >> 1;
            float4 v = *(const float4*)(abase + (size_t)(m0 + m) * ldaa);
            uint32_t h0, l0, h1, l1;
            cvt_split2(v.x, v.y, h0, l0);
            cvt_split2(v.z, v.w, h1, l1);
            Ah[m][pc] = h0; Ah[m][pc + 1] = h1;
            Al[m][pc] = l0; Al[m][pc + 1] = l1;
            float4 w = *(const float4*)(Bm + (size_t)(n0 + m) * ldb + k0 + k4);
            cvt_split2(w.x, w.y, h0, l0);
            cvt_split2(w.z, w.w, h1, l1);
            Bh[m][pc] = h0; Bh[m][pc + 1] = h1;
            Bl[m][pc] = l0; Bl[m][pc + 1] = l1;
        }
        __syncthreads();

        #pragma unroll
        for (int kk = 0; kk < 2; kk++) {
            const int pc = kk * 8;
            uint32_t ah[2][4], al[2][4];
            #pragma unroll
            for (int mt = 0; mt < 2; mt++) {
                #pragma unroll
                for (int q = 0; q < 4; q++) {
                    const int row = wm + mt * 16 + g + (q & 1) * 8;
                    const int col = pc + t + (q >> 1) * 4;
                    ah[mt][q] = Ah[row][col];
                    al[mt][q] = Al[row][col];
                }
            }
            #pragma unroll
            for (int nf = 0; nf < 8; nf++) {
                const int rb = wn + nf * 8 + g;
                const uint32_t bh0 = Bh[rb][pc + t], bh1 = Bh[rb][pc + t + 4];
                const uint32_t bl0 = Bl[rb][pc + t], bl1 = Bl[rb][pc + t + 4];
                #pragma unroll
                for (int mt = 0; mt < 2; mt++) {
                    mma_bf16(acc[mt][nf], ah[mt][0], ah[mt][1], ah[mt][2], ah[mt][3], bh0, bh1);
                    mma_bf16(acc[mt][nf], ah[mt][0], ah[mt][1], ah[mt][2], ah[mt][3], bl0, bl1);
                    mma_bf16(acc[mt][nf], al[mt][0], al[mt][1], al[mt][2], al[mt][3], bh0, bh1);
                }
            }
        }
    }
}

// ---------------------------------------------------------------------------
// Kernel 1: 5 head projections, grid.z selects which. V written transposed.
// ---------------------------------------------------------------------------
__global__ __launch_bounds__(256) void proj_kernel(
    const float* __restrict__ qa_in, const float* __restrict__ qg_in,
    const float* __restrict__ ka_in, const float* __restrict__ kg_in,
    const float* __restrict__ va_in,
    const float* __restrict__ Wqa, const float* __restrict__ Wqg,
    const float* __restrict__ Wka, const float* __restrict__ Wkg,
    const float* __restrict__ Wva,
    const float* __restrict__ bqa, const float* __restrict__ bqg,
    const float* __restrict__ bka, const float* __restrict__ bkg,
    const float* __restrict__ bva)
{
    __shared__ uint32_t Ah[128][20], Al[128][20], Bh[128][20], Bl[128][20];
    const int p = blockIdx.z;
    const float* A; const float* W; const float* bias;
    if      (p == 0) { A = qa_in; W = Wqa; bias = bqa; }
    else if (p == 1) { A = qg_in; W = Wqg; bias = bqg; }
    else if (p == 2) { A = ka_in; W = Wka; bias = bka; }
    else if (p == 3) { A = kg_in; W = Wkg; bias = bkg; }
    else             { A = va_in; W = Wva; bias = bva; }

    const int m0 = blockIdx.y * 128;
    const int n0 = blockIdx.x * 128;
    float acc[2][8][4] = {};
    gemm_bf16_body(A, 1024, nullptr, 1 << 30, W, 1024, 1024, m0, n0, acc,
                   (SmT)Ah, (SmT)Al, (SmT)Bh, (SmT)Bl);

    const int lane = threadIdx.x & 31, warp = threadIdx.x >> 5;
    const int wm = (warp & 3) * 32, wn = (warp >> 2) * 64;
    const int g = lane >> 2, t = lane & 3;

    #pragma unroll
    for (int nf = 0; nf < 8; nf++) {
        const int n  = n0 + wn + nf * 8 + 2 * t;
        const int h  = n >> 6, jj = n & 63;
        const float bx = bias[n], by = bias[n + 1];
        #pragma unroll
        for (int mt = 0; mt < 2; mt++) {
            #pragma unroll
            for (int h2 = 0; h2 < 2; h2++) {
                const int m = m0 + wm + mt * 16 + g + h2 * 8;
                const int b = m >> 10, s = m & 1023;
                const size_t bhh = (size_t)(b * 16 + h);
                float2 v;
                v.x = acc[mt][nf][h2 * 2 + 0] + bx;
                v.y = acc[mt][nf][h2 * 2 + 1] + by;
                if      (p == 0) *(float2*)&g_Q[(bhh * 1024 + s) * 128 + jj]      = v;
                else if (p == 1) *(float2*)&g_Q[(bhh * 1024 + s) * 128 + 64 + jj] = v;
                else if (p == 2) *(float2*)&g_K[(bhh * 1024 + s) * 128 + jj]      = v;
                else if (p == 3) *(float2*)&g_K[(bhh * 1024 + s) * 128 + 64 + jj] = v;
                else {
                    g_V[(bhh * 64 + jj)     * 1024 + s] = v.x;   // transposed
                    g_V[(bhh * 64 + jj + 1) * 1024 + s] = v.y;
                }
            }
        }
    }
}

// ---------------------------------------------------------------------------
// Kernel 2: gate = sigmoid(concat(query_a, query_g) @ Wgate^T + bgate), K=2048
// ---------------------------------------------------------------------------
__global__ __launch_bounds__(256) void gate_kernel(
    const float* __restrict__ qa_in, const float* __restrict__ qg_in,
    const float* __restrict__ Wgate, const float* __restrict__ bgate)
{
    __shared__ uint32_t Ah[128][20], Al[128][20], Bh[128][20], Bl[128][20];
    const int m0 = blockIdx.y * 128;
    const int n0 = blockIdx.x * 128;
    float acc[2][8][4] = {};
    gemm_bf16_body(qa_in, 1024, qg_in, 1024, Wgate, 2048, 2048, m0, n0, acc,
                   (SmT)Ah, (SmT)Al, (SmT)Bh, (SmT)Bl);

    const int lane = threadIdx.x & 31, warp = threadIdx.x >> 5;
    const int wm = (warp & 3) * 32, wn = (warp >> 2) * 64;
    const int g = lane >> 2, t = lane & 3;

    #pragma unroll
    for (int nf = 0; nf < 8; nf++) {
        const int n = n0 + wn + nf * 8 + 2 * t;
        const float bx = bgate[n], by = bgate[n + 1];
        #pragma unroll
        for (int mt = 0; mt < 2; mt++) {
            #pragma unroll
            for (int h2 = 0; h2 < 2; h2++) {
                const int m = m0 + wm + mt * 16 + g + h2 * 8;
                float2 v;
                v.x = 1.0f / (1.0f + __expf(-(acc[mt][nf][h2 * 2 + 0] + bx)));
                v.y = 1.0f / (1.0f + __expf(-(acc[mt][nf][h2 * 2 + 1] + by)));
                *(float2*)&g_G[(size_t)m * 1024 + n] = v;
            }
        }
    }
}

// ---------------------------------------------------------------------------
// Kernel 3: fused flash attention. One block = (bh, 128-row m-tile).
// 8 warps: 4m x 2n for S (warp 32x64); each warp accumulates a partial
// O (32x64) over its own 64-key slice; partials combined in the epilogue.
// Dynamic smem (176128 B): Qh/Ql [128][68], Kh/Kl [128][68], Vh/Vl [64][68],
// redmax/redsum [2][128].
// ---------------------------------------------------------------------------
#define ATTN_SMEM 176128

__global__ __launch_bounds__(256) void attn_kernel(const int* __restrict__ mask)
{
    extern __shared__ char smem[];
    uint32_t (*Qh)[68] = (uint32_t(*)[68])(smem);
    uint32_t (*Ql)[68] = (uint32_t(*)[68])(smem + 34816);
    uint32_t (*Kh)[68] = (uint32_t(*)[68])(smem + 69632);
    uint32_t (*Kl)[68] = (uint32_t(*)[68])(smem + 104448);
    uint32_t (*Vh)[68] = (uint32_t(*)[68])(smem + 139264);
    uint32_t (*Vl)[68] = (uint32_t(*)[68])(smem + 156672);
    float* redmax = (float*)(smem + 174080);   // [2][128]
    float* redsum = (float*)(smem + 175104);   // [2][128]
    float* Osum   = (float*)(smem + 69632);    // reuse K region, [128][66]

    const int tid  = threadIdx.x;
    const int warp = tid >> 5, lane = tid & 31;
    const int wm = (warp & 3) * 32;
    const int wn = (warp >> 2);          // 0 or 1
    const int g  = lane >> 2;
    const int t  = lane & 3;

    const int bh = blockIdx.y;
    const int b  = bh >> 4, h = bh & 15;
    const int m0 = blockIdx.x * 128;

    const float* Qg = g_Q + ((size_t)bh << 17);
    const float* Kg = g_K + ((size_t)bh << 17);
    const float* Vg = g_V + ((size_t)bh << 16);

    // Loader mapping: 32 lanes cover one 128-float row segment
    const int lrow = tid >> 5;           // 0..7
    const int col4 = (tid & 31) * 4;
    const int pcw  = (tid & 31) * 2;

    // ---- load Q tile once ----
    #pragma unroll
    for (int i = 0; i < 16; i++) {
        const int r = lrow + i * 8;
        float4 v = *(const float4*)(Qg + (size_t)(m0 + r) * 128 + col4);
        uint32_t h0, l0, h1, l1;
        cvt_split2(v.x, v.y, h0, l0);
        cvt_split2(v.z, v.w, h1, l1);
        Qh[r][pcw] = h0; Qh[r][pcw + 1] = h1;
        Ql[r][pcw] = l0; Ql[r][pcw + 1] = l1;
    }

    float o[2][8][4] = {};
    float mrun[2][2] = {{-INFINITY, -INFINITY}, {-INFINITY, -INFINITY}};
    float lrun[2][2] = {};
    const float scale = 0.08838834764831845f;   // 1/sqrt(128)

    for (int nt = 0; nt < 8; nt++) {
        const int n0 = nt * 128;
        __syncthreads();   // prior iter's smem reads (and Q store) complete

        // ---- load K tile (128x128) and V^T tile (64x128) ----
        #pragma unroll
        for (int i = 0; i < 16; i++) {
            const int r = lrow + i * 8;
            float4 v = *(const float4*)(Kg + (size_t)(n0 + r) * 128 + col4);
            uint32_t h0, l0, h1, l1;
            cvt_split2(v.x, v.y, h0, l0);
            cvt_split2(v.z, v.w, h1, l1);
            Kh[r][pcw] = h0; Kh[r][pcw + 1] = h1;
            Kl[r][pcw] = l0; Kl[r][pcw + 1] = l1;
        }
        #pragma unroll
        for (int i = 0; i < 8; i++) {
            const int r = lrow + i * 8;
            float4 v = *(const float4*)(Vg + (size_t)r * 1024 + n0 + col4);
            uint32_t h0, l0, h1, l1;
            cvt_split2(v.x, v.y, h0, l0);
            cvt_split2(v.z, v.w, h1, l1);
            Vh[r][pcw] = h0; Vh[r][pcw + 1] = h1;
            Vl[r][pcw] = l0; Vl[r][pcw + 1] = l1;
        }
        __syncthreads();

        // ---- S = Q K^T (warp slice 32m x 64n) ----
        float s[2][8][4] = {};
        #pragma unroll
        for (int ks = 0; ks < 8; ks++) {
            const int pc = ks * 8;
            uint32_t ah[2][4], al[2][4];
            #pragma unroll
            for (int mt = 0; mt < 2; mt++) {
                #pragma unroll
                for (int q = 0; q < 4; q++) {
                    const int row = wm + mt * 16 + g + (q & 1) * 8;
                    const int col = pc + t + (q >> 1) * 4;
                    ah[mt][q] = Qh[row][col];
                    al[mt][q] = Ql[row][col];
                }
            }
            #pragma unroll
            for (int nf = 0; nf < 8; nf++) {
                const int rb = wn * 64 + nf * 8 + g;
                const uint32_t bh0 = Kh[rb][pc + t], bh1 = Kh[rb][pc + t + 4];
                const uint32_t bl0 = Kl[rb][pc + t], bl1 = Kl[rb][pc + t + 4];
                #pragma unroll
                for (int mt = 0; mt < 2; mt++) {
                    mma_bf16(s[mt][nf], ah[mt][0], ah[mt][1], ah[mt][2], ah[mt][3], bh0, bh1);
                    mma_bf16(s[mt][nf], ah[mt][0], ah[mt][1], ah[mt][2], ah[mt][3], bl0, bl1);
                    mma_bf16(s[mt][nf], al[mt][0], al[mt][1], al[mt][2], al[mt][3], bh0, bh1);
                }
            }
        }

        // ---- scale + mask + thread-local row max ----
        float pm[2][2];
        #pragma unroll
        for (int mt = 0; mt < 2; mt++) {
            #pragma unroll
            for (int h2 = 0; h2 < 2; h2++) {
                const int rglob = m0 + wm + mt * 16 + g + h2 * 8;
                float mx = -INFINITY;
                #pragma unroll
                for (int nf = 0; nf < 8; nf++) {
                    const int ncol = n0 + wn * 64 + nf * 8 + 2 * t;
                    const int2 mk = *(const int2*)(mask + (((size_t)b << 20) + ((size_t)rglob << 10) + ncol));
                    float v0 = s[mt][nf][h2 * 2 + 0] * scale;
                    float v1 = s[mt][nf][h2 * 2 + 1] * scale;
                    if (mk.x == 0) v0 = -1e9f;
                    if (mk.y == 0) v1 = -1e9f;
                    s[mt][nf][h2 * 2 + 0] = v0;
                    s[mt][nf][h2 * 2 + 1] = v1;
                    mx = fmaxf(mx, fmaxf(v0, v1));
                }
                pm[mt][h2] = mx;
            }
        }
        // reduce across the 4 lanes of the row group
        #pragma unroll
        for (int mt = 0; mt < 2; mt++)
            #pragma unroll
            for (int h2 = 0; h2 < 2; h2++) {
                pm[mt][h2] = fmaxf(pm[mt][h2], __shfl_xor_sync(0xffffffffu, pm[mt][h2], 1));
                pm[mt][h2] = fmaxf(pm[mt][h2], __shfl_xor_sync(0xffffffffu, pm[mt][h2], 2));
            }
        if (t == 0) {
            #pragma unroll
            for (int mt = 0; mt < 2; mt++)
                #pragma unroll
                for (int h2 = 0; h2 < 2; h2++)
                    redmax[wn * 128 + wm + mt * 16 + g + h2 * 8] = pm[mt][h2];
        }
        __syncthreads();

        // ---- m_new, alpha, exponentiate, partial sums, rescale O ----
        float alpha[2][2], psum[2][2];
        #pragma unroll
        for (int mt = 0; mt < 2; mt++) {
            #pragma unroll
            for (int h2 = 0; h2 < 2; h2++) {
                const int rl = wm + mt * 16 + g + h2 * 8;
                const float mtile = fmaxf(redmax[rl], redmax[128 + rl]);
                const float mnew  = fmaxf(mrun[mt][h2], mtile);
                alpha[mt][h2] = __expf(mrun[mt][h2] - mnew);
                mrun[mt][h2]  = mnew;
                float ps = 0.0f;
                #pragma unroll
                for (int nf = 0; nf < 8; nf++) {
                    float p0 = __expf(s[mt][nf][h2 * 2 + 0] - mnew);
                    float p1 = __expf(s[mt][nf][h2 * 2 + 1] - mnew);
                    s[mt][nf][h2 * 2 + 0] = p0;
                    s[mt][nf][h2 * 2 + 1] = p1;
                    ps += p0 + p1;
                }
                psum[mt][h2] = ps;
            }
        }
        #pragma unroll
        for (int mt = 0; mt < 2; mt++)
            #pragma unroll
            for (int nf = 0; nf < 8; nf++)
                #pragma unroll
                for (int e = 0; e < 4; e++)
                    o[mt][nf][e] *= alpha[mt][e >> 1];
        #pragma unroll
        for (int mt = 0; mt < 2; mt++)
            #pragma unroll
            for (int h2 = 0; h2 < 2; h2++) {
                psum[mt][h2] += __shfl_xor_sync(0xffffffffu, psum[mt][h2], 1);
                psum[mt][h2] += __shfl_xor_sync(0xffffffffu, psum[mt][h2], 2);
            }
        if (t == 0) {
            #pragma unroll
            for (int mt = 0; mt < 2; mt++)
                #pragma unroll
                for (int h2 = 0; h2 < 2; h2++)
                    redsum[wn * 128 + wm + mt * 16 + g + h2 * 8] = psum[mt][h2];
        }
        __syncthreads();
        #pragma unroll
        for (int mt = 0; mt < 2; mt++)
            #pragma unroll
            for (int h2 = 0; h2 < 2; h2++) {
                const int rl = wm + mt * 16 + g + h2 * 8;
                lrun[mt][h2] = lrun[mt][h2] * alpha[mt][h2] + redsum[rl] + redsum[128 + rl];
            }

        // ---- O += P V (P from registers; warp's k-slice = its 64 n-cols) ----
        #pragma unroll
        for (int ks2 = 0; ks2 < 4; ks2++) {
            uint32_t ah[2][4], al[2][4];
            #pragma unroll
            for (int mt = 0; mt < 2; mt++) {
                cvt_split2(s[mt][2 * ks2][0],     s[mt][2 * ks2][1],     ah[mt][0], al[mt][0]);
                cvt_split2(s[mt][2 * ks2][2],     s[mt][2 * ks2][3],     ah[mt][1], al[mt][1]);
                cvt_split2(s[mt][2 * ks2 + 1][0], s[mt][2 * ks2 + 1][1], ah[mt][2], al[mt][2]);
                cvt_split2(s[mt][2 * ks2 + 1][2], s[mt][2 * ks2 + 1][3], ah[mt][3], al[mt][3]);
            }
            const int vcol = wn * 32 + ks2 * 8 + t;
            #pragma unroll
            for (int nf = 0; nf < 8; nf++) {
                const int rv = nf * 8 + g;
                const uint32_t bh0 = Vh[rv][vcol], bh1 = Vh[rv][vcol + 4];
                const uint32_t bl0 = Vl[rv][vcol], bl1 = Vl[rv][vcol + 4];
                #pragma unroll
                for (int mt = 0; mt < 2; mt++) {
                    mma_bf16(o[mt][nf], ah[mt][0], ah[mt][1], ah[mt][2], ah[mt][3], bh0, bh1);
                    mma_bf16(o[mt][nf], ah[mt][0], ah[mt][1], ah[mt][2], ah[mt][3], bl0, bl1);
                    mma_bf16(o[mt][nf], al[mt][0], al[mt][1], al[mt][2], al[mt][3], bh0, bh1);
                }
            }
        }
    }

    // ---- epilogue: combine the two n-warps' partial O, divide by l, store ----
    __syncthreads();   // all smem reads done; reuse K region as Osum
    if (wn == 1) {
        #pragma unroll
        for (int mt = 0; mt < 2; mt++)
            #pragma unroll
            for (int h2 = 0; h2 < 2; h2++) {
                const int rl = wm + mt * 16 + g + h2 * 8;
                #pragma unroll
                for (int nf = 0; nf < 8; nf++) {
                    float2 v;
                    v.x = o[mt][nf][h2 * 2 + 0];
                    v.y = o[mt][nf][h2 * 2 + 1];
                    *(float2*)&Osum[rl * 66 + nf * 8 + 2 * t] = v;
                }
            }
    }
    __syncthreads();
    if (wn == 0) {
        #pragma unroll
        for (int mt = 0; mt < 2; mt++)
            #pragma unroll
            for (int h2 = 0; h2 < 2; h2++) {
                const int rl = wm + mt * 16 + g + h2 * 8;
                const float inv = 1.0f / lrun[mt][h2];
                #pragma unroll
                for (int nf = 0; nf < 8; nf++) {
                    const int c = nf * 8 + 2 * t;
                    float2 p = *(float2*)&Osum[rl * 66 + c];
                    float2 v;
                    v.x = (o[mt][nf][h2 * 2 + 0] + p.x) * inv;
                    v.y = (o[mt][nf][h2 * 2 + 1] + p.y) * inv;
                    *(float2*)&g_X[(size_t)(b * 1024 + m0 + rl) * 1024 + h * 64 + c] = v;
                }
            }
    }
}

// ---------------------------------------------------------------------------
// Kernel 4: out = gate * (X @ Winfo^T + binfo)
// ---------------------------------------------------------------------------
__global__ __launch_bounds__(256) void info_kernel(
    const float* __restrict__ Winfo, const float* __restrict__ binfo,
    float* __restrict__ out)
{
    __shared__ uint32_t Ah[128][20], Al[128][20], Bh[128][20], Bl[128][20];
    const int m0 = blockIdx.y * 128;
    const int n0 = blockIdx.x * 128;
    float acc[2][8][4] = {};
    gemm_bf16_body(g_X, 1024, nullptr, 1 << 30, Winfo, 1024, 1024, m0, n0, acc,
                   (SmT)Ah, (SmT)Al, (SmT)Bh, (SmT)Bl);

    const int lane = threadIdx.x & 31, warp = threadIdx.x >> 5;
    const int wm = (warp & 3) * 32, wn = (warp >> 2) * 64;
    const int g = lane >> 2, t = lane & 3;

    #pragma unroll
    for (int nf = 0; nf < 8; nf++) {
        const int n = n0 + wn + nf * 8 + 2 * t;
        const float bx = binfo[n], by = binfo[n + 1];
        #pragma unroll
        for (int mt = 0; mt < 2; mt++) {
            #pragma unroll
            for (int h2 = 0; h2 < 2; h2++) {
                const int m = m0 + wm + mt * 16 + g + h2 * 8;
                const float2 gg = *(const float2*)&g_G[(size_t)m * 1024 + n];
                float2 v;
                v.x = gg.x * (acc[mt][nf][h2 * 2 + 0] + bx);
                v.y = gg.y * (acc[mt][nf][h2 * 2 + 1] + by);
                *(float2*)&out[(size_t)m * 1024 + n] = v;
            }
        }
    }
}

// ---------------------------------------------------------------------------
extern "C" void kernel_launch(void* const* d_in, const int* in_sizes, int n_in,
                              void* d_out, int out_size)
{
    (void)in_sizes; (void)n_in; (void)out_size;
    const float* query_g = (const float*)d_in[0];
    const float* key_g   = (const float*)d_in[1];
    const float* query_a = (const float*)d_in[2];
    const float* key_a   = (const float*)d_in[3];
    const float* value_a = (const float*)d_in[4];
    const int*   mask    = (const int*)  d_in[5];
    const float* Wqg = (const float*)d_in[6];  const float* bqg = (const float*)d_in[7];
    const float* Wkg = (const float*)d_in[8];  const float* bkg = (const float*)d_in[9];
    const float* Wqa = (const float*)d_in[10]; const float* bqa = (const float*)d_in[11];
    const float* Wka = (const float*)d_in[12]; const float* bka = (const float*)d_in[13];
    const float* Wva = (const float*)d_in[14]; const float* bva = (const float*)d_in[15];
    const float* Wgate = (const float*)d_in[16]; const float* bgate = (const float*)d_in[17];
    const float* Winfo = (const float*)d_in[18]; const float* binfo = (const float*)d_in[19];

    static int smem_set = 0;
    if (!smem_set) {
        cudaFuncSetAttribute(attn_kernel, cudaFuncAttributeMaxDynamicSharedMemorySize, ATTN_SMEM);
        smem_set = 1;
    }

    dim3 blk(256);
    proj_kernel<<<dim3(8, 32, 5), blk>>>(query_a, query_g, key_a, key_g, value_a,
                                         Wqa, Wqg, Wka, Wkg, Wva,
                                         bqa, bqg, bka, bkg, bva);
    gate_kernel<<<dim3(8, 32, 1), blk>>>(query_a, query_g, Wgate, bgate);
    attn_kernel<<<dim3(8, 64), blk, ATTN_SMEM>>>(mask);
    info_kernel<<<dim3(8, 32, 1), blk>>>(Winfo, binfo, (float*)d_out);
}

// round 4
// speedup vs baseline: 2.3464x; 1.2219x over previous
#include <cuda_runtime.h>
#include <cuda_bf16.h>
#include <math.h>
#include <stdint.h>

// Problem constants
#define B_  4
#define S_  1024
#define D_  1024
#define H_  16
#define BH  64     // B*H

// Scratch
static __device__ float g_Q[(size_t)BH * S_ * 128];   // [bh, s, 128] (qa|qg)
static __device__ float g_K[(size_t)BH * S_ * 128];   // [bh, s, 128] (ka|kg)
static __device__ float g_V[(size_t)BH * 64 * S_];    // TRANSPOSED [bh, j(64), s(1024)]
static __device__ float g_X[(size_t)B_ * S_ * D_];    // attn out [token][1024]
static __device__ float g_G[(size_t)B_ * S_ * D_];    // gate

// ---------------------------------------------------------------------------
// bf16 split helpers: x = hi + lo. 3-term mma (hh+hl+lh) leaves ~eps^2 error.
// ---------------------------------------------------------------------------
__device__ __forceinline__ void cvt_split2(float x, float y, uint32_t &hi, uint32_t &lo) {
    __nv_bfloat16 hx = __float2bfloat16_rn(x);
    __nv_bfloat16 hy = __float2bfloat16_rn(y);
    float rx = x - __bfloat162float(hx);
    float ry = y - __bfloat162float(hy);
    __nv_bfloat16 lx = __float2bfloat16_rn(rx);
    __nv_bfloat16 ly = __float2bfloat16_rn(ry);
    hi = (uint32_t)__bfloat16_as_ushort(hx) | ((uint32_t)__bfloat16_as_ushort(hy) << 16);
    lo = (uint32_t)__bfloat16_as_ushort(lx) | ((uint32_t)__bfloat16_as_ushort(ly) << 16);
}

__device__ __forceinline__ void mma_bf16(float* c,
    uint32_t a0, uint32_t a1, uint32_t a2, uint32_t a3,
    uint32_t b0, uint32_t b1)
{
    asm volatile(
        "mma.sync.aligned.m16n8k16.row.col.f32.bf16.bf16.f32 "
        "{%0,%1,%2,%3},{%4,%5,%6,%7},{%8,%9},{%0,%1,%2,%3};"
        : "+f"(c[0]), "+f"(c[1]), "+f"(c[2]), "+f"(c[3])
        : "r"(a0), "r"(a1), "r"(a2), "r"(a3), "r"(b0), "r"(b1));
}

// ---------------------------------------------------------------------------
// Pipelined 128x128 C-tile GEMM body: C = A[m0:, :K] * B[n0:, :K]^T.
// Register-prefetch pipeline: LDG of tile k+1 issues before the MMA loop of
// tile k, so global latency hides under ~96 tensor ops.
// 256 thr = 8 warps (4m x 2n), warp tile 32x64, mma m16n8k16 bf16 3-split.
// ---------------------------------------------------------------------------
typedef uint32_t (*SmT)[20];

__device__ __forceinline__ void load_ab_regs(
    const float* __restrict__ A, int lda,
    const float* __restrict__ A2, int ksplit,
    const float* __restrict__ Bm, int ldb,
    int m0, int n0, int k0, int k4, int ar,
    float4 va[4], float4 vb[4])
{
    const int colA = k0 + k4;
    const float* abase; int ldaa;
    if (colA >= ksplit) { abase = A2 + (colA - ksplit); ldaa = 1024; }
    else                { abase = A  + colA;            ldaa = lda;  }
    #pragma unroll
    for (int i = 0; i < 4; i++) {
        const int m = ar + i * 32;
        va[i] = *(const float4*)(abase + (size_t)(m0 + m) * ldaa);
        vb[i] = *(const float4*)(Bm + (size_t)(n0 + m) * ldb + k0 + k4);
    }
}

__device__ __forceinline__ void store_tile(
    const float4 va[4], const float4 vb[4], int k4, int ar,
    SmT Ah, SmT Al, SmT Bh, SmT Bl)
{
    const int pc = k4 >> 1;
    #pragma unroll
    for (int i = 0; i < 4; i++) {
        const int m = ar + i * 32;
        uint32_t h0, l0, h1, l1;
        cvt_split2(va[i].x, va[i].y, h0, l0);
        cvt_split2(va[i].z, va[i].w, h1, l1);
        Ah[m][pc] = h0; Ah[m][pc + 1] = h1;
        Al[m][pc] = l0; Al[m][pc + 1] = l1;
        cvt_split2(vb[i].x, vb[i].y, h0, l0);
        cvt_split2(vb[i].z, vb[i].w, h1, l1);
        Bh[m][pc] = h0; Bh[m][pc + 1] = h1;
        Bl[m][pc] = l0; Bl[m][pc + 1] = l1;
    }
}

__device__ __forceinline__ void gemm_bf16_body(
    const float* __restrict__ A, int lda,
    const float* __restrict__ A2, int ksplit,
    const float* __restrict__ Bm, int ldb,
    int K, int m0, int n0,
    float acc[2][8][4],
    SmT Ah, SmT Al, SmT Bh, SmT Bl)
{
    const int tid  = threadIdx.x;
    const int warp = tid >> 5, lane = tid & 31;
    const int wm = (warp & 3) * 32;
    const int wn = (warp >> 2) * 64;
    const int g  = lane >> 2;
    const int t  = lane & 3;
    const int k4 = (tid & 7) * 4;   // float col within 32-wide k tile
    const int ar = tid >> 3;        // 0..31

    float4 va[4], vb[4];
    load_ab_regs(A, lda, A2, ksplit, Bm, ldb, m0, n0, 0, k4, ar, va, vb);

    for (int k0 = 0; k0 < K; k0 += 32) {
        __syncthreads();            // consumers of previous tile done
        store_tile(va, vb, k4, ar, Ah, Al, Bh, Bl);
        __syncthreads();

        if (k0 + 32 < K)            // prefetch next tile; LDG overlaps MMA below
            load_ab_regs(A, lda, A2, ksplit, Bm, ldb, m0, n0, k0 + 32, k4, ar, va, vb);

        #pragma unroll
        for (int kk = 0; kk < 2; kk++) {
            const int pc = kk * 8;
            uint32_t ah[2][4], al[2][4];
            #pragma unroll
            for (int mt = 0; mt < 2; mt++) {
                #pragma unroll
                for (int q = 0; q < 4; q++) {
                    const int row = wm + mt * 16 + g + (q & 1) * 8;
                    const int col = pc + t + (q >> 1) * 4;
                    ah[mt][q] = Ah[row][col];
                    al[mt][q] = Al[row][col];
                }
            }
            #pragma unroll
            for (int nf = 0; nf < 8; nf++) {
                const int rb = wn + nf * 8 + g;
                const uint32_t bh0 = Bh[rb][pc + t], bh1 = Bh[rb][pc + t + 4];
                const uint32_t bl0 = Bl[rb][pc + t], bl1 = Bl[rb][pc + t + 4];
                #pragma unroll
                for (int mt = 0; mt < 2; mt++) {
                    mma_bf16(acc[mt][nf], ah[mt][0], ah[mt][1], ah[mt][2], ah[mt][3], bh0, bh1);
                    mma_bf16(acc[mt][nf], ah[mt][0], ah[mt][1], ah[mt][2], ah[mt][3], bl0, bl1);
                    mma_bf16(acc[mt][nf], al[mt][0], al[mt][1], al[mt][2], al[mt][3], bh0, bh1);
                }
            }
        }
    }
}

// ---------------------------------------------------------------------------
// Kernel 1: 5 head projections, grid.z selects which. V written transposed.
// ---------------------------------------------------------------------------
__global__ __launch_bounds__(256, 2) void proj_kernel(
    const float* __restrict__ qa_in, const float* __restrict__ qg_in,
    const float* __restrict__ ka_in, const float* __restrict__ kg_in,
    const float* __restrict__ va_in,
    const float* __restrict__ Wqa, const float* __restrict__ Wqg,
    const float* __restrict__ Wka, const float* __restrict__ Wkg,
    const float* __restrict__ Wva,
    const float* __restrict__ bqa, const float* __restrict__ bqg,
    const float* __restrict__ bka, const float* __restrict__ bkg,
    const float* __restrict__ bva)
{
    __shared__ uint32_t Ah[128][20], Al[128][20], Bh[128][20], Bl[128][20];
    const int p = blockIdx.z;
    const float* A; const float* W; const float* bias;
    if      (p == 0) { A = qa_in; W = Wqa; bias = bqa; }
    else if (p == 1) { A = qg_in; W = Wqg; bias = bqg; }
    else if (p == 2) { A = ka_in; W = Wka; bias = bka; }
    else if (p == 3) { A = kg_in; W = Wkg; bias = bkg; }
    else             { A = va_in; W = Wva; bias = bva; }

    const int m0 = blockIdx.y * 128;
    const int n0 = blockIdx.x * 128;
    float acc[2][8][4] = {};
    gemm_bf16_body(A, 1024, nullptr, 1 << 30, W, 1024, 1024, m0, n0, acc,
                   (SmT)Ah, (SmT)Al, (SmT)Bh, (SmT)Bl);

    const int lane = threadIdx.x & 31, warp = threadIdx.x >> 5;
    const int wm = (warp & 3) * 32, wn = (warp >> 2) * 64;
    const int g = lane >> 2, t = lane & 3;

    #pragma unroll
    for (int nf = 0; nf < 8; nf++) {
        const int n  = n0 + wn + nf * 8 + 2 * t;
        const int h  = n >> 6, jj = n & 63;
        const float bx = bias[n], by = bias[n + 1];
        #pragma unroll
        for (int mt = 0; mt < 2; mt++) {
            #pragma unroll
            for (int h2 = 0; h2 < 2; h2++) {
                const int m = m0 + wm + mt * 16 + g + h2 * 8;
                const int b = m >> 10, s = m & 1023;
                const size_t bhh = (size_t)(b * 16 + h);
                float2 v;
                v.x = acc[mt][nf][h2 * 2 + 0] + bx;
                v.y = acc[mt][nf][h2 * 2 + 1] + by;
                if      (p == 0) *(float2*)&g_Q[(bhh * 1024 + s) * 128 + jj]      = v;
                else if (p == 1) *(float2*)&g_Q[(bhh * 1024 + s) * 128 + 64 + jj] = v;
                else if (p == 2) *(float2*)&g_K[(bhh * 1024 + s) * 128 + jj]      = v;
                else if (p == 3) *(float2*)&g_K[(bhh * 1024 + s) * 128 + 64 + jj] = v;
                else {
                    g_V[(bhh * 64 + jj)     * 1024 + s] = v.x;   // transposed
                    g_V[(bhh * 64 + jj + 1) * 1024 + s] = v.y;
                }
            }
        }
    }
}

// ---------------------------------------------------------------------------
// Kernel 2: gate = sigmoid(concat(query_a, query_g) @ Wgate^T + bgate), K=2048
// ---------------------------------------------------------------------------
__global__ __launch_bounds__(256, 2) void gate_kernel(
    const float* __restrict__ qa_in, const float* __restrict__ qg_in,
    const float* __restrict__ Wgate, const float* __restrict__ bgate)
{
    __shared__ uint32_t Ah[128][20], Al[128][20], Bh[128][20], Bl[128][20];
    const int m0 = blockIdx.y * 128;
    const int n0 = blockIdx.x * 128;
    float acc[2][8][4] = {};
    gemm_bf16_body(qa_in, 1024, qg_in, 1024, Wgate, 2048, 2048, m0, n0, acc,
                   (SmT)Ah, (SmT)Al, (SmT)Bh, (SmT)Bl);

    const int lane = threadIdx.x & 31, warp = threadIdx.x >> 5;
    const int wm = (warp & 3) * 32, wn = (warp >> 2) * 64;
    const int g = lane >> 2, t = lane & 3;

    #pragma unroll
    for (int nf = 0; nf < 8; nf++) {
        const int n = n0 + wn + nf * 8 + 2 * t;
        const float bx = bgate[n], by = bgate[n + 1];
        #pragma unroll
        for (int mt = 0; mt < 2; mt++) {
            #pragma unroll
            for (int h2 = 0; h2 < 2; h2++) {
                const int m = m0 + wm + mt * 16 + g + h2 * 8;
                float2 v;
                v.x = 1.0f / (1.0f + __expf(-(acc[mt][nf][h2 * 2 + 0] + bx)));
                v.y = 1.0f / (1.0f + __expf(-(acc[mt][nf][h2 * 2 + 1] + by)));
                *(float2*)&g_G[(size_t)m * 1024 + n] = v;
            }
        }
    }
}

// ---------------------------------------------------------------------------
// Kernel 3: fused flash attention. One block = (bh, 128-row m-tile).
// 8 warps: 4m x 2n for S; each warp accumulates partial O over its 64-key
// slice; partials combined in the epilogue.
// ---------------------------------------------------------------------------
#define ATTN_SMEM 176128

__global__ __launch_bounds__(256) void attn_kernel(const int* __restrict__ mask)
{
    extern __shared__ char smem[];
    uint32_t (*Qh)[68] = (uint32_t(*)[68])(smem);
    uint32_t (*Ql)[68] = (uint32_t(*)[68])(smem + 34816);
    uint32_t (*Kh)[68] = (uint32_t(*)[68])(smem + 69632);
    uint32_t (*Kl)[68] = (uint32_t(*)[68])(smem + 104448);
    uint32_t (*Vh)[68] = (uint32_t(*)[68])(smem + 139264);
    uint32_t (*Vl)[68] = (uint32_t(*)[68])(smem + 156672);
    float* redmax = (float*)(smem + 174080);   // [2][128]
    float* redsum = (float*)(smem + 175104);   // [2][128]
    float* Osum   = (float*)(smem + 69632);    // reuse K region, [128][66]

    const int tid  = threadIdx.x;
    const int warp = tid >> 5, lane = tid & 31;
    const int wm = (warp & 3) * 32;
    const int wn = (warp >> 2);          // 0 or 1
    const int g  = lane >> 2;
    const int t  = lane & 3;

    const int bh = blockIdx.y;
    const int b  = bh >> 4, h = bh & 15;
    const int m0 = blockIdx.x * 128;

    const float* Qg = g_Q + ((size_t)bh << 17);
    const float* Kg = g_K + ((size_t)bh << 17);
    const float* Vg = g_V + ((size_t)bh << 16);

    const int lrow = tid >> 5;           // 0..7
    const int col4 = (tid & 31) * 4;
    const int pcw  = (tid & 31) * 2;

    // ---- load Q tile once ----
    #pragma unroll
    for (int i = 0; i < 16; i++) {
        const int r = lrow + i * 8;
        float4 v = *(const float4*)(Qg + (size_t)(m0 + r) * 128 + col4);
        uint32_t h0, l0, h1, l1;
        cvt_split2(v.x, v.y, h0, l0);
        cvt_split2(v.z, v.w, h1, l1);
        Qh[r][pcw] = h0; Qh[r][pcw + 1] = h1;
        Ql[r][pcw] = l0; Ql[r][pcw + 1] = l1;
    }

    float o[2][8][4] = {};
    float mrun[2][2] = {{-INFINITY, -INFINITY}, {-INFINITY, -INFINITY}};
    float lrun[2][2] = {};
    const float scale = 0.08838834764831845f;   // 1/sqrt(128)

    for (int nt = 0; nt < 8; nt++) {
        const int n0 = nt * 128;
        __syncthreads();

        #pragma unroll
        for (int i = 0; i < 16; i++) {
            const int r = lrow + i * 8;
            float4 v = *(const float4*)(Kg + (size_t)(n0 + r) * 128 + col4);
            uint32_t h0, l0, h1, l1;
            cvt_split2(v.x, v.y, h0, l0);
            cvt_split2(v.z, v.w, h1, l1);
            Kh[r][pcw] = h0; Kh[r][pcw + 1] = h1;
            Kl[r][pcw] = l0; Kl[r][pcw + 1] = l1;
        }
        #pragma unroll
        for (int i = 0; i < 8; i++) {
            const int r = lrow + i * 8;
            float4 v = *(const float4*)(Vg + (size_t)r * 1024 + n0 + col4);
            uint32_t h0, l0, h1, l1;
            cvt_split2(v.x, v.y, h0, l0);
            cvt_split2(v.z, v.w, h1, l1);
            Vh[r][pcw] = h0; Vh[r][pcw + 1] = h1;
            Vl[r][pcw] = l0; Vl[r][pcw + 1] = l1;
        }
        __syncthreads();

        // ---- S = Q K^T ----
        float s[2][8][4] = {};
        #pragma unroll
        for (int ks = 0; ks < 8; ks++) {
            const int pc = ks * 8;
            uint32_t ah[2][4], al[2][4];
            #pragma unroll
            for (int mt = 0; mt < 2; mt++) {
                #pragma unroll
                for (int q = 0; q < 4; q++) {
                    const int row = wm + mt * 16 + g + (q & 1) * 8;
                    const int col = pc + t + (q >> 1) * 4;
                    ah[mt][q] = Qh[row][col];
                    al[mt][q] = Ql[row][col];
                }
            }
            #pragma unroll
            for (int nf = 0; nf < 8; nf++) {
                const int rb = wn * 64 + nf * 8 + g;
                const uint32_t bh0 = Kh[rb][pc + t], bh1 = Kh[rb][pc + t + 4];
                const uint32_t bl0 = Kl[rb][pc + t], bl1 = Kl[rb][pc + t + 4];
                #pragma unroll
                for (int mt = 0; mt < 2; mt++) {
                    mma_bf16(s[mt][nf], ah[mt][0], ah[mt][1], ah[mt][2], ah[mt][3], bh0, bh1);
                    mma_bf16(s[mt][nf], ah[mt][0], ah[mt][1], ah[mt][2], ah[mt][3], bl0, bl1);
                    mma_bf16(s[mt][nf], al[mt][0], al[mt][1], al[mt][2], al[mt][3], bh0, bh1);
                }
            }
        }

        // ---- scale + mask + row max ----
        float pm[2][2];
        #pragma unroll
        for (int mt = 0; mt < 2; mt++) {
            #pragma unroll
            for (int h2 = 0; h2 < 2; h2++) {
                const int rglob = m0 + wm + mt * 16 + g + h2 * 8;
                float mx = -INFINITY;
                #pragma unroll
                for (int nf = 0; nf < 8; nf++) {
                    const int ncol = n0 + wn * 64 + nf * 8 + 2 * t;
                    const int2 mk = *(const int2*)(mask + (((size_t)b << 20) + ((size_t)rglob << 10) + ncol));
                    float v0 = s[mt][nf][h2 * 2 + 0] * scale;
                    float v1 = s[mt][nf][h2 * 2 + 1] * scale;
                    if (mk.x == 0) v0 = -1e9f;
                    if (mk.y == 0) v1 = -1e9f;
                    s[mt][nf][h2 * 2 + 0] = v0;
                    s[mt][nf][h2 * 2 + 1] = v1;
                    mx = fmaxf(mx, fmaxf(v0, v1));
                }
                pm[mt][h2] = mx;
            }
        }
        #pragma unroll
        for (int mt = 0; mt < 2; mt++)
            #pragma unroll
            for (int h2 = 0; h2 < 2; h2++) {
                pm[mt][h2] = fmaxf(pm[mt][h2], __shfl_xor_sync(0xffffffffu, pm[mt][h2], 1));
                pm[mt][h2] = fmaxf(pm[mt][h2], __shfl_xor_sync(0xffffffffu, pm[mt][h2], 2));
            }
        if (t == 0) {
            #pragma unroll
            for (int mt = 0; mt < 2; mt++)
                #pragma unroll
                for (int h2 = 0; h2 < 2; h2++)
                    redmax[wn * 128 + wm + mt * 16 + g + h2 * 8] = pm[mt][h2];
        }
        __syncthreads();

        // ---- running stats, exponentiate, rescale O ----
        float alpha[2][2], psum[2][2];
        #pragma unroll
        for (int mt = 0; mt < 2; mt++) {
            #pragma unroll
            for (int h2 = 0; h2 < 2; h2++) {
                const int rl = wm + mt * 16 + g + h2 * 8;
                const float mtile = fmaxf(redmax[rl], redmax[128 + rl]);
                const float mnew  = fmaxf(mrun[mt][h2], mtile);
                alpha[mt][h2] = __expf(mrun[mt][h2] - mnew);
                mrun[mt][h2]  = mnew;
                float ps = 0.0f;
                #pragma unroll
                for (int nf = 0; nf < 8; nf++) {
                    float p0 = __expf(s[mt][nf][h2 * 2 + 0] - mnew);
                    float p1 = __expf(s[mt][nf][h2 * 2 + 1] - mnew);
                    s[mt][nf][h2 * 2 + 0] = p0;
                    s[mt][nf][h2 * 2 + 1] = p1;
                    ps += p0 + p1;
                }
                psum[mt][h2] = ps;
            }
        }
        #pragma unroll
        for (int mt = 0; mt < 2; mt++)
            #pragma unroll
            for (int nf = 0; nf < 8; nf++)
                #pragma unroll
                for (int e = 0; e < 4; e++)
                    o[mt][nf][e] *= alpha[mt][e >> 1];
        #pragma unroll
        for (int mt = 0; mt < 2; mt++)
            #pragma unroll
            for (int h2 = 0; h2 < 2; h2++) {
                psum[mt][h2] += __shfl_xor_sync(0xffffffffu, psum[mt][h2], 1);
                psum[mt][h2] += __shfl_xor_sync(0xffffffffu, psum[mt][h2], 2);
            }
        if (t == 0) {
            #pragma unroll
            for (int mt = 0; mt < 2; mt++)
                #pragma unroll
                for (int h2 = 0; h2 < 2; h2++)
                    redsum[wn * 128 + wm + mt * 16 + g + h2 * 8] = psum[mt][h2];
        }
        __syncthreads();
        #pragma unroll
        for (int mt = 0; mt < 2; mt++)
            #pragma unroll
            for (int h2 = 0; h2 < 2; h2++) {
                const int rl = wm + mt * 16 + g + h2 * 8;
                lrun[mt][h2] = lrun[mt][h2] * alpha[mt][h2] + redsum[rl] + redsum[128 + rl];
            }

        // ---- O += P V ----
        #pragma unroll
        for (int ks2 = 0; ks2 < 4; ks2++) {
            uint32_t ah[2][4], al[2][4];
            #pragma unroll
            for (int mt = 0; mt < 2; mt++) {
                cvt_split2(s[mt][2 * ks2][0],     s[mt][2 * ks2][1],     ah[mt][0], al[mt][0]);
                cvt_split2(s[mt][2 * ks2][2],     s[mt][2 * ks2][3],     ah[mt][1], al[mt][1]);
                cvt_split2(s[mt][2 * ks2 + 1][0], s[mt][2 * ks2 + 1][1], ah[mt][2], al[mt][2]);
                cvt_split2(s[mt][2 * ks2 + 1][2], s[mt][2 * ks2 + 1][3], ah[mt][3], al[mt][3]);
            }
            const int vcol = wn * 32 + ks2 * 8 + t;
            #pragma unroll
            for (int nf = 0; nf < 8; nf++) {
                const int rv = nf * 8 + g;
                const uint32_t bh0 = Vh[rv][vcol], bh1 = Vh[rv][vcol + 4];
                const uint32_t bl0 = Vl[rv][vcol], bl1 = Vl[rv][vcol + 4];
                #pragma unroll
                for (int mt = 0; mt < 2; mt++) {
                    mma_bf16(o[mt][nf], ah[mt][0], ah[mt][1], ah[mt][2], ah[mt][3], bh0, bh1);
                    mma_bf16(o[mt][nf], ah[mt][0], ah[mt][1], ah[mt][2], ah[mt][3], bl0, bl1);
                    mma_bf16(o[mt][nf], al[mt][0], al[mt][1], al[mt][2], al[mt][3], bh0, bh1);
                }
            }
        }
    }

    // ---- epilogue ----
    __syncthreads();
    if (wn == 1) {
        #pragma unroll
        for (int mt = 0; mt < 2; mt++)
            #pragma unroll
            for (int h2 = 0; h2 < 2; h2++) {
                const int rl = wm + mt * 16 + g + h2 * 8;
                #pragma unroll
                for (int nf = 0; nf < 8; nf++) {
                    float2 v;
                    v.x = o[mt][nf][h2 * 2 + 0];
                    v.y = o[mt][nf][h2 * 2 + 1];
                    *(float2*)&Osum[rl * 66 + nf * 8 + 2 * t] = v;
                }
            }
    }
    __syncthreads();
    if (wn == 0) {
        #pragma unroll
        for (int mt = 0; mt < 2; mt++)
            #pragma unroll
            for (int h2 = 0; h2 < 2; h2++) {
                const int rl = wm + mt * 16 + g + h2 * 8;
                const float inv = 1.0f / lrun[mt][h2];
                #pragma unroll
                for (int nf = 0; nf < 8; nf++) {
                    const int c = nf * 8 + 2 * t;
                    float2 p = *(float2*)&Osum[rl * 66 + c];
                    float2 v;
                    v.x = (o[mt][nf][h2 * 2 + 0] + p.x) * inv;
                    v.y = (o[mt][nf][h2 * 2 + 1] + p.y) * inv;
                    *(float2*)&g_X[(size_t)(b * 1024 + m0 + rl) * 1024 + h * 64 + c] = v;
                }
            }
    }
}

// ---------------------------------------------------------------------------
// Kernel 4: out = gate * (X @ Winfo^T + binfo)
// ---------------------------------------------------------------------------
__global__ __launch_bounds__(256, 2) void info_kernel(
    const float* __restrict__ Winfo, const float* __restrict__ binfo,
    float* __restrict__ out)
{
    __shared__ uint32_t Ah[128][20], Al[128][20], Bh[128][20], Bl[128][20];
    const int m0 = blockIdx.y * 128;
    const int n0 = blockIdx.x * 128;
    float acc[2][8][4] = {};
    gemm_bf16_body(g_X, 1024, nullptr, 1 << 30, Winfo, 1024, 1024, m0, n0, acc,
                   (SmT)Ah, (SmT)Al, (SmT)Bh, (SmT)Bl);

    const int lane = threadIdx.x & 31, warp = threadIdx.x >> 5;
    const int wm = (warp & 3) * 32, wn = (warp >> 2) * 64;
    const int g = lane >> 2, t = lane & 3;

    #pragma unroll
    for (int nf = 0; nf < 8; nf++) {
        const int n = n0 + wn + nf * 8 + 2 * t;
        const float bx = binfo[n], by = binfo[n + 1];
        #pragma unroll
        for (int mt = 0; mt < 2; mt++) {
            #pragma unroll
            for (int h2 = 0; h2 < 2; h2++) {
                const int m = m0 + wm + mt * 16 + g + h2 * 8;
                const float2 gg = *(const float2*)&g_G[(size_t)m * 1024 + n];
                float2 v;
                v.x = gg.x * (acc[mt][nf][h2 * 2 + 0] + bx);
                v.y = gg.y * (acc[mt][nf][h2 * 2 + 1] + by);
                *(float2*)&out[(size_t)m * 1024 + n] = v;
            }
        }
    }
}

// ---------------------------------------------------------------------------
extern "C" void kernel_launch(void* const* d_in, const int* in_sizes, int n_in,
                              void* d_out, int out_size)
{
    (void)in_sizes; (void)n_in; (void)out_size;
    const float* query_g = (const float*)d_in[0];
    const float* key_g   = (const float*)d_in[1];
    const float* query_a = (const float*)d_in[2];
    const float* key_a   = (const float*)d_in[3];
    const float* value_a = (const float*)d_in[4];
    const int*   mask    = (const int*)  d_in[5];
    const float* Wqg = (const float*)d_in[6];  const float* bqg = (const float*)d_in[7];
    const float* Wkg = (const float*)d_in[8];  const float* bkg = (const float*)d_in[9];
    const float* Wqa = (const float*)d_in[10]; const float* bqa = (const float*)d_in[11];
    const float* Wka = (const float*)d_in[12]; const float* bka = (const float*)d_in[13];
    const float* Wva = (const float*)d_in[14]; const float* bva = (const float*)d_in[15];
    const float* Wgate = (const float*)d_in[16]; const float* bgate = (const float*)d_in[17];
    const float* Winfo = (const float*)d_in[18]; const float* binfo = (const float*)d_in[19];

    static int smem_set = 0;
    if (!smem_set) {
        cudaFuncSetAttribute(attn_kernel, cudaFuncAttributeMaxDynamicSharedMemorySize, ATTN_SMEM);
        smem_set = 1;
    }

    dim3 blk(256);
    proj_kernel<<<dim3(8, 32, 5), blk>>>(query_a, query_g, key_a, key_g, value_a,
                                         Wqa, Wqg, Wka, Wkg, Wva,
                                         bqa, bqg, bka, bkg, bva);
    gate_kernel<<<dim3(8, 32, 1), blk>>>(query_a, query_g, Wgate, bgate);
    attn_kernel<<<dim3(8, 64), blk, ATTN_SMEM>>>(mask);
    info_kernel<<<dim3(8, 32, 1), blk>>>(Winfo, binfo, (float*)d_out);
}